// round 10
// baseline (speedup 1.0000x reference)
#include <cuda_runtime.h>
#include <cstdint>

#define THREADS 512
#define TE      256       // edges per tile
#define NPAIR   128       // edge pairs per tile
#define PADK    146       // per-pair k-stride in ull units (even -> 16B alignment)
#define KIN     144
#define HID     64
#define NEG     0.1f
#define LNEPS   1e-5f

typedef unsigned long long ull;

// smem layout (floats)
#define X2_U   (NPAIR * PADK)            // 18688 ull = 37376 floats
#define W1_F   (KIN * HID)               // 9216
#define W2_F   (HID * HID)               // 4096
#define VEC_F  512
#define SMEM_F (2 * X2_U + W1_F + W2_F + VEC_F)   // 51200 floats
#define SMEM_BYTES (SMEM_F * 4)                   // 204800 B

__device__ int g_is32;

// ---------------------------------------------------------------------------
// Detect whether edge_index is really int64 or silently-demoted int32.
__global__ void check_idx_kernel(const long long* __restrict__ idx, long long n,
                                 unsigned long long n_nodes) {
    __shared__ int bad;
    if (threadIdx.x == 0) bad = 0;
    __syncthreads();
    int local = 0;
    for (long long i = threadIdx.x; i < n; i += blockDim.x) {
        if ((unsigned long long)idx[i] >= n_nodes) local = 1;
    }
    if (local) bad = 1;
    __syncthreads();
    if (threadIdx.x == 0) g_is32 = bad;
}

// ---------------------------------------------------------------------------
__device__ __forceinline__ void fma2(ull& d, ull a, ull b) {
    asm("fma.rn.f32x2 %0, %1, %2, %0;" : "+l"(d) : "l"(a), "l"(b));
}
__device__ __forceinline__ void add2(ull& d, ull b) {
    asm("add.rn.f32x2 %0, %0, %1;" : "+l"(d) : "l"(b));
}
__device__ __forceinline__ ull dup2(float v) {
    ull r;
    asm("mov.b64 %0, {%1, %1};" : "=l"(r) : "f"(v));
    return r;
}

// ---------------------------------------------------------------------------
// GEMM micro-tile: 2 edge-pairs (4 edges) x 8 cols per thread (512 threads).
// Weights laid out per k-row as [j0..3 of cg0..7][j4..7 of cg0..7] so a
// quarter-warp's LDS.128 covers a contiguous, conflict-free 128B.
template<int K>
__device__ __forceinline__ void gemm_tile(const ull* __restrict__ X2u,
                                          const float* __restrict__ Wd,
                                          ull acc[2][8], int p0, int cg4) {
    const ull* xr = X2u + (size_t)p0 * PADK;
    #pragma unroll 2
    for (int k = 0; k < K; k += 2) {
        ulonglong2 xa = *(const ulonglong2*)(xr + k);
        ulonglong2 xb = *(const ulonglong2*)(xr + PADK + k);
        const float* w = Wd + (size_t)k * 64 + cg4;
        float4 wa0 = *(const float4*)(w);
        float4 wb0 = *(const float4*)(w + 32);
        float4 wa1 = *(const float4*)(w + 64);
        float4 wb1 = *(const float4*)(w + 96);
        {
            ull w0 = dup2(wa0.x), w1 = dup2(wa0.y), w2 = dup2(wa0.z), w3 = dup2(wa0.w);
            ull w4 = dup2(wb0.x), w5 = dup2(wb0.y), w6 = dup2(wb0.z), w7 = dup2(wb0.w);
            fma2(acc[0][0], xa.x, w0); fma2(acc[1][0], xb.x, w0);
            fma2(acc[0][1], xa.x, w1); fma2(acc[1][1], xb.x, w1);
            fma2(acc[0][2], xa.x, w2); fma2(acc[1][2], xb.x, w2);
            fma2(acc[0][3], xa.x, w3); fma2(acc[1][3], xb.x, w3);
            fma2(acc[0][4], xa.x, w4); fma2(acc[1][4], xb.x, w4);
            fma2(acc[0][5], xa.x, w5); fma2(acc[1][5], xb.x, w5);
            fma2(acc[0][6], xa.x, w6); fma2(acc[1][6], xb.x, w6);
            fma2(acc[0][7], xa.x, w7); fma2(acc[1][7], xb.x, w7);
        }
        {
            ull w0 = dup2(wa1.x), w1 = dup2(wa1.y), w2 = dup2(wa1.z), w3 = dup2(wa1.w);
            ull w4 = dup2(wb1.x), w5 = dup2(wb1.y), w6 = dup2(wb1.z), w7 = dup2(wb1.w);
            fma2(acc[0][0], xa.y, w0); fma2(acc[1][0], xb.y, w0);
            fma2(acc[0][1], xa.y, w1); fma2(acc[1][1], xb.y, w1);
            fma2(acc[0][2], xa.y, w2); fma2(acc[1][2], xb.y, w2);
            fma2(acc[0][3], xa.y, w3); fma2(acc[1][3], xb.y, w3);
            fma2(acc[0][4], xa.y, w4); fma2(acc[1][4], xb.y, w4);
            fma2(acc[0][5], xa.y, w5); fma2(acc[1][5], xb.y, w5);
            fma2(acc[0][6], xa.y, w6); fma2(acc[1][6], xb.y, w6);
            fma2(acc[0][7], xa.y, w7); fma2(acc[1][7], xb.y, w7);
        }
    }
}

// Epilogue: add bias (packed) and store the f32x2 accumulator pair directly
// into the interleaved tile at k-slot = column. Zero unpacking.
__device__ __forceinline__ void epi_store(ull acc[2][8], ull* __restrict__ X2u,
                                          const float* __restrict__ bias,
                                          int p0, int c0) {
    #pragma unroll
    for (int j = 0; j < 8; j++) {
        ull b = dup2(bias[c0 + j]);
        #pragma unroll
        for (int i = 0; i < 2; i++) {
            add2(acc[i][j], b);
            X2u[(size_t)(p0 + i) * PADK + (c0 + j)] = acc[i][j];
        }
    }
}

// ---------------------------------------------------------------------------
extern "C" __global__ void __launch_bounds__(THREADS, 1)
edge_mlp_kernel(const float* __restrict__ nodes,
                const void*  __restrict__ eidx,
                const float* __restrict__ eattr,
                const float* __restrict__ W1g, const float* __restrict__ b1g,
                const float* __restrict__ g1g, const float* __restrict__ be1g,
                const float* __restrict__ W2g, const float* __restrict__ b2g,
                const float* __restrict__ g2g, const float* __restrict__ be2g,
                const float* __restrict__ W3g, const float* __restrict__ b3g,
                float* __restrict__ out, long long E)
{
    extern __shared__ float sm[];
    ull*   X2u = (ull*)sm;
    float* X2f = sm;
    float* Wd1 = sm + 2 * X2_U;
    float* Wd2 = Wd1 + W1_F;
    float* vec = Wd2 + W2_F;
    float* b1s = vec;        float* g1s = vec + 64;  float* be1s = vec + 128;
    float* b2s = vec + 192;  float* g2s = vec + 256; float* be2s = vec + 320;
    float* W3s = vec + 384;

    const int tid = threadIdx.x;

    // Stage weights with per-row swizzle:
    // element (k, c=cg*8+j) -> k*64 + (j&4 ? 32 : 0) + cg*4 + (j&3)
    for (int i = tid; i < W1_F; i += THREADS) {
        int k = i >> 6, c = i & 63;
        int cg = c >> 3, j = c & 7;
        Wd1[k * 64 + ((j & 4) ? 32 : 0) + cg * 4 + (j & 3)] = W1g[i];
    }
    for (int i = tid; i < W2_F; i += THREADS) {
        int k = i >> 6, c = i & 63;
        int cg = c >> 3, j = c & 7;
        Wd2[k * 64 + ((j & 4) ? 32 : 0) + cg * 4 + (j & 3)] = W2g[i];
    }
    if (tid < 64) {
        b1s[tid] = b1g[tid];  g1s[tid] = g1g[tid];  be1s[tid] = be1g[tid];
        b2s[tid] = b2g[tid];  g2s[tid] = g2g[tid];  be2s[tid] = be2g[tid];
        W3s[tid] = W3g[tid];
    }
    const float b3v = b3g[0];
    const int is32 = g_is32;
    __syncthreads();

    const long long ntiles = (E + TE - 1) / TE;
    const int cg = tid & 7, eg = tid >> 3;          // eg in 0..63
    const int c0 = cg * 8, cg4 = cg * 4, p0 = eg * 2;
    // LN / staging mapping: 2 threads per edge
    const int le = tid >> 1, lh = tid & 1;          // edge-in-tile, half
    const int lp = le >> 1, lpar = le & 1;          // pair, parity

    for (long long tile = blockIdx.x; tile < ntiles; tile += gridDim.x) {
        const long long Eb = tile * (long long)TE;

        // ---- stage X tile: 2 threads per edge (lh=0: src + attr lo, lh=1: dst + attr hi)
        {
            long long e = Eb + le;
            if (e > E - 1) e = E - 1;
            long long row;
            if (is32) {
                const int* I = (const int*)eidx;
                row = (long long)I[lh ? (E + e) : e];
            } else {
                const long long* I = (const long long*)eidx;
                row = I[lh ? (E + e) : e];
            }
            float* xb = X2f + lpar;
            const float4* rp = (const float4*)(nodes + row * 64);
            const int cbase = lh * 64;
            #pragma unroll
            for (int m = 0; m < 16; m++) {
                float4 v = rp[m];
                size_t b = ((size_t)lp * PADK + cbase + m * 4) * 2;
                xb[b] = v.x; xb[b + 2] = v.y; xb[b + 4] = v.z; xb[b + 6] = v.w;
            }
            const float4* ap = (const float4*)(eattr + e * 16);
            #pragma unroll
            for (int m = 0; m < 2; m++) {
                float4 v = ap[lh * 2 + m];
                size_t b = ((size_t)lp * PADK + 128 + (lh * 2 + m) * 4) * 2;
                xb[b] = v.x; xb[b + 2] = v.y; xb[b + 4] = v.z; xb[b + 6] = v.w;
            }
        }
        __syncthreads();  // S1: X staged

        // ---- GEMM1: (256 x 144) @ (144 x 64)
        ull acc[2][8];
        #pragma unroll
        for (int i = 0; i < 2; i++)
            #pragma unroll
            for (int j = 0; j < 8; j++) acc[i][j] = 0ULL;
        gemm_tile<KIN>(X2u, Wd1, acc, p0, cg4);
        __syncthreads();  // S2: all X reads done (epi overwrites k-slots 0..63)
        epi_store(acc, X2u, b1s, p0, c0);
        __syncthreads();  // S3: raw H complete

        // ---- LN1 + leaky, in place. 2 threads per edge; each owns float4s
        //      m = lh*16 .. lh*16+15 (k = 32*lh .. 32*lh+31); shfl combines sums.
        {
            const float4* rp = (const float4*)(X2f + (size_t)lp * PADK * 2);
            float s = 0.f, ss = 0.f;
            #pragma unroll
            for (int mm = 0; mm < 16; mm++) {
                float4 v = rp[lh * 16 + mm];
                float a = lpar ? v.y : v.x;     // k = 2m
                float b = lpar ? v.w : v.z;     // k = 2m+1
                s += a + b;  ss += a * a + b * b;
            }
            s  += __shfl_xor_sync(0xffffffffu, s, 1);
            ss += __shfl_xor_sync(0xffffffffu, ss, 1);
            float mu  = s * 0.015625f;
            float var = ss * 0.015625f - mu * mu;
            float rs  = rsqrtf(var + LNEPS);
            #pragma unroll
            for (int mm = 0; mm < 16; mm++) {
                int m = lh * 16 + mm;
                float4 v = rp[m];
                float a = lpar ? v.y : v.x;
                float b = lpar ? v.w : v.z;
                int k0 = 2 * m;
                float na = (a - mu) * rs * g1s[k0] + be1s[k0];
                float nb = (b - mu) * rs * g1s[k0 + 1] + be1s[k0 + 1];
                na = fmaxf(na, NEG * na);  nb = fmaxf(nb, NEG * nb);
                size_t bidx = ((size_t)lp * PADK + k0) * 2 + lpar;
                X2f[bidx]     = na;
                X2f[bidx + 2] = nb;
            }
        }
        __syncthreads();  // S4: H normalized, ready for GEMM2

        // ---- GEMM2: (256 x 64) @ (64 x 64)
        #pragma unroll
        for (int i = 0; i < 2; i++)
            #pragma unroll
            for (int j = 0; j < 8; j++) acc[i][j] = 0ULL;
        gemm_tile<HID>(X2u, Wd2, acc, p0, cg4);
        __syncthreads();  // S5: all H reads done
        epi_store(acc, X2u, b2s, p0, c0);
        __syncthreads();  // S6: raw H2 complete

        // ---- LN2 + leaky + dot(W3) + b3 -> global out (2 threads per edge)
        {
            const float4* rp = (const float4*)(X2f + (size_t)lp * PADK * 2);
            float s = 0.f, ss = 0.f;
            #pragma unroll
            for (int mm = 0; mm < 16; mm++) {
                float4 v = rp[lh * 16 + mm];
                float a = lpar ? v.y : v.x;
                float b = lpar ? v.w : v.z;
                s += a + b;  ss += a * a + b * b;
            }
            s  += __shfl_xor_sync(0xffffffffu, s, 1);
            ss += __shfl_xor_sync(0xffffffffu, ss, 1);
            float mu  = s * 0.015625f;
            float var = ss * 0.015625f - mu * mu;
            float rs  = rsqrtf(var + LNEPS);
            float accO = 0.f;
            #pragma unroll
            for (int mm = 0; mm < 16; mm++) {
                int m = lh * 16 + mm;
                float4 v = rp[m];
                float a = lpar ? v.y : v.x;
                float b = lpar ? v.w : v.z;
                int k0 = 2 * m;
                float na = (a - mu) * rs * g2s[k0] + be2s[k0];
                float nb = (b - mu) * rs * g2s[k0 + 1] + be2s[k0 + 1];
                na = fmaxf(na, NEG * na);  nb = fmaxf(nb, NEG * nb);
                accO += na * W3s[k0] + nb * W3s[k0 + 1];
            }
            accO += __shfl_xor_sync(0xffffffffu, accO, 1);
            long long e = Eb + le;
            if (lh == 0 && e < E) out[e] = accO + b3v;
        }
        __syncthreads();  // S7: LN2 reads done before next tile's staging
    }
}

// ---------------------------------------------------------------------------
extern "C" void kernel_launch(void* const* d_in, const int* in_sizes, int n_in,
                              void* d_out, int out_size) {
    const float* nodes = (const float*)d_in[0];
    const void*  eidx  = d_in[1];
    const float* eattr = (const float*)d_in[2];
    const float* W1 = (const float*)d_in[3];
    const float* b1 = (const float*)d_in[4];
    const float* g1 = (const float*)d_in[5];
    const float* be1 = (const float*)d_in[6];
    const float* W2 = (const float*)d_in[7];
    const float* b2 = (const float*)d_in[8];
    const float* g2 = (const float*)d_in[9];
    const float* be2 = (const float*)d_in[10];
    const float* W3 = (const float*)d_in[11];
    const float* b3 = (const float*)d_in[12];
    float* out = (float*)d_out;

    const long long E = (long long)in_sizes[2] / 16;
    const unsigned long long n_nodes = (unsigned long long)in_sizes[0] / 64;
    if (E <= 0) return;

    cudaFuncSetAttribute(edge_mlp_kernel,
                         cudaFuncAttributeMaxDynamicSharedMemorySize, SMEM_BYTES);

    int nsm = 148;
    cudaDeviceGetAttribute(&nsm, cudaDevAttrMultiProcessorCount, 0);
    if (nsm <= 0) nsm = 148;

    long long ncheck = E < 2048 ? E : 2048;
    check_idx_kernel<<<1, 256>>>((const long long*)eidx, ncheck, n_nodes);

    long long ntiles = (E + TE - 1) / TE;
    int grid = (ntiles < (long long)nsm) ? (int)ntiles : nsm;
    edge_mlp_kernel<<<grid, THREADS, SMEM_BYTES>>>(
        nodes, eidx, eattr, W1, b1, g1, be1, W2, b2, g2, be2, W3, b3, out, E);
}

// round 13
// speedup vs baseline: 1.1174x; 1.1174x over previous
#include <cuda_runtime.h>
#include <cstdint>

#define THREADS 256
#define TE      256       // edges per tile
#define NPAIR   128       // edge pairs per tile
#define PADK    146       // per-pair k-stride in ull units (even -> 16B alignment)
#define KIN     144
#define HID     64
#define NEG     0.1f
#define LNEPS   1e-5f

typedef unsigned long long ull;

// smem layout (floats)
#define X2_U   (NPAIR * PADK)            // 18688 ull = 37376 floats
#define W1_F   (KIN * HID)               // 9216
#define W2_F   (HID * HID)               // 4096
#define VEC_F  512
#define SMEM_F (2 * X2_U + W1_F + W2_F + VEC_F)   // 51200 floats
#define SMEM_BYTES (SMEM_F * 4)                   // 204800 B

__device__ int g_is32;

// ---------------------------------------------------------------------------
// Detect whether edge_index is really int64 or silently-demoted int32.
__global__ void check_idx_kernel(const long long* __restrict__ idx, long long n,
                                 unsigned long long n_nodes) {
    __shared__ int bad;
    if (threadIdx.x == 0) bad = 0;
    __syncthreads();
    int local = 0;
    for (long long i = threadIdx.x; i < n; i += blockDim.x) {
        if ((unsigned long long)idx[i] >= n_nodes) local = 1;
    }
    if (local) bad = 1;
    __syncthreads();
    if (threadIdx.x == 0) g_is32 = bad;
}

// ---------------------------------------------------------------------------
__device__ __forceinline__ void fma2(ull& d, ull a, ull b) {
    asm("fma.rn.f32x2 %0, %1, %2, %0;" : "+l"(d) : "l"(a), "l"(b));
}
__device__ __forceinline__ void add2(ull& d, ull b) {
    asm("add.rn.f32x2 %0, %0, %1;" : "+l"(d) : "l"(b));
}
__device__ __forceinline__ ull dup2(float v) {
    ull r;
    asm("mov.b64 %0, {%1, %1};" : "=l"(r) : "f"(v));
    return r;
}

// ---------------------------------------------------------------------------
// Software-pipelined GEMM micro-tile: 4 edge-pairs (8 edges) x 8 cols per
// thread, 256 threads. Double-buffered register prefetch with distance 2 k.
// Weights laid out per k-row as [j0..3 of cg0..7][j4..7 of cg0..7] so a
// quarter-warp's LDS.128 covers a contiguous, conflict-free 128B.

struct KBuf {
    ulonglong2 xa, xb, xc, xd;    // 4 pair-rows, 2 k each
    float4 wa0, wb0, wa1, wb1;    // 2 weight rows (k, k+1), this thread's 8 cols
};

__device__ __forceinline__ void load_buf(KBuf& b, const ull* __restrict__ xr,
                                         const float* __restrict__ Wd,
                                         int k, int cg4) {
    b.xa = *(const ulonglong2*)(xr + k);
    b.xb = *(const ulonglong2*)(xr + PADK + k);
    b.xc = *(const ulonglong2*)(xr + 2 * PADK + k);
    b.xd = *(const ulonglong2*)(xr + 3 * PADK + k);
    const float* w = Wd + (size_t)k * 64 + cg4;
    b.wa0 = *(const float4*)(w);
    b.wb0 = *(const float4*)(w + 32);
    b.wa1 = *(const float4*)(w + 64);
    b.wb1 = *(const float4*)(w + 96);
}

__device__ __forceinline__ void compute_buf(const KBuf& b, ull acc[4][8]) {
    {
        ull w0 = dup2(b.wa0.x), w1 = dup2(b.wa0.y), w2 = dup2(b.wa0.z), w3 = dup2(b.wa0.w);
        ull w4 = dup2(b.wb0.x), w5 = dup2(b.wb0.y), w6 = dup2(b.wb0.z), w7 = dup2(b.wb0.w);
        fma2(acc[0][0], b.xa.x, w0); fma2(acc[1][0], b.xb.x, w0);
        fma2(acc[2][0], b.xc.x, w0); fma2(acc[3][0], b.xd.x, w0);
        fma2(acc[0][1], b.xa.x, w1); fma2(acc[1][1], b.xb.x, w1);
        fma2(acc[2][1], b.xc.x, w1); fma2(acc[3][1], b.xd.x, w1);
        fma2(acc[0][2], b.xa.x, w2); fma2(acc[1][2], b.xb.x, w2);
        fma2(acc[2][2], b.xc.x, w2); fma2(acc[3][2], b.xd.x, w2);
        fma2(acc[0][3], b.xa.x, w3); fma2(acc[1][3], b.xb.x, w3);
        fma2(acc[2][3], b.xc.x, w3); fma2(acc[3][3], b.xd.x, w3);
        fma2(acc[0][4], b.xa.x, w4); fma2(acc[1][4], b.xb.x, w4);
        fma2(acc[2][4], b.xc.x, w4); fma2(acc[3][4], b.xd.x, w4);
        fma2(acc[0][5], b.xa.x, w5); fma2(acc[1][5], b.xb.x, w5);
        fma2(acc[2][5], b.xc.x, w5); fma2(acc[3][5], b.xd.x, w5);
        fma2(acc[0][6], b.xa.x, w6); fma2(acc[1][6], b.xb.x, w6);
        fma2(acc[2][6], b.xc.x, w6); fma2(acc[3][6], b.xd.x, w6);
        fma2(acc[0][7], b.xa.x, w7); fma2(acc[1][7], b.xb.x, w7);
        fma2(acc[2][7], b.xc.x, w7); fma2(acc[3][7], b.xd.x, w7);
    }
    {
        ull w0 = dup2(b.wa1.x), w1 = dup2(b.wa1.y), w2 = dup2(b.wa1.z), w3 = dup2(b.wa1.w);
        ull w4 = dup2(b.wb1.x), w5 = dup2(b.wb1.y), w6 = dup2(b.wb1.z), w7 = dup2(b.wb1.w);
        fma2(acc[0][0], b.xa.y, w0); fma2(acc[1][0], b.xb.y, w0);
        fma2(acc[2][0], b.xc.y, w0); fma2(acc[3][0], b.xd.y, w0);
        fma2(acc[0][1], b.xa.y, w1); fma2(acc[1][1], b.xb.y, w1);
        fma2(acc[2][1], b.xc.y, w1); fma2(acc[3][1], b.xd.y, w1);
        fma2(acc[0][2], b.xa.y, w2); fma2(acc[1][2], b.xb.y, w2);
        fma2(acc[2][2], b.xc.y, w2); fma2(acc[3][2], b.xd.y, w2);
        fma2(acc[0][3], b.xa.y, w3); fma2(acc[1][3], b.xb.y, w3);
        fma2(acc[2][3], b.xc.y, w3); fma2(acc[3][3], b.xd.y, w3);
        fma2(acc[0][4], b.xa.y, w4); fma2(acc[1][4], b.xb.y, w4);
        fma2(acc[2][4], b.xc.y, w4); fma2(acc[3][4], b.xd.y, w4);
        fma2(acc[0][5], b.xa.y, w5); fma2(acc[1][5], b.xb.y, w5);
        fma2(acc[2][5], b.xc.y, w5); fma2(acc[3][5], b.xd.y, w5);
        fma2(acc[0][6], b.xa.y, w6); fma2(acc[1][6], b.xb.y, w6);
        fma2(acc[2][6], b.xc.y, w6); fma2(acc[3][6], b.xd.y, w6);
        fma2(acc[0][7], b.xa.y, w7); fma2(acc[1][7], b.xb.y, w7);
        fma2(acc[2][7], b.xc.y, w7); fma2(acc[3][7], b.xd.y, w7);
    }
}

// K must be a multiple of 4 (144, 64 both are).
template<int K>
__device__ __forceinline__ void gemm_tile(const ull* __restrict__ X2u,
                                          const float* __restrict__ Wd,
                                          ull acc[4][8], int p0, int cg4) {
    const ull* xr = X2u + (size_t)p0 * PADK;
    KBuf b0, b1;
    load_buf(b0, xr, Wd, 0, cg4);
    load_buf(b1, xr, Wd, 2, cg4);
    #pragma unroll 1
    for (int k = 0; k < K - 4; k += 4) {
        compute_buf(b0, acc);
        load_buf(b0, xr, Wd, k + 4, cg4);
        compute_buf(b1, acc);
        load_buf(b1, xr, Wd, k + 6, cg4);
    }
    compute_buf(b0, acc);
    compute_buf(b1, acc);
}

// Epilogue: add bias (packed) and store the f32x2 accumulator pair directly
// into the interleaved tile at k-slot = column. Zero unpacking.
__device__ __forceinline__ void epi_store(ull acc[4][8], ull* __restrict__ X2u,
                                          const float* __restrict__ bias,
                                          int p0, int c0) {
    #pragma unroll
    for (int j = 0; j < 8; j++) {
        ull b = dup2(bias[c0 + j]);
        #pragma unroll
        for (int i = 0; i < 4; i++) {
            add2(acc[i][j], b);
            X2u[(size_t)(p0 + i) * PADK + (c0 + j)] = acc[i][j];
        }
    }
}

// ---------------------------------------------------------------------------
extern "C" __global__ void __launch_bounds__(THREADS, 1)
edge_mlp_kernel(const float* __restrict__ nodes,
                const void*  __restrict__ eidx,
                const float* __restrict__ eattr,
                const float* __restrict__ W1g, const float* __restrict__ b1g,
                const float* __restrict__ g1g, const float* __restrict__ be1g,
                const float* __restrict__ W2g, const float* __restrict__ b2g,
                const float* __restrict__ g2g, const float* __restrict__ be2g,
                const float* __restrict__ W3g, const float* __restrict__ b3g,
                float* __restrict__ out, long long E)
{
    extern __shared__ float sm[];
    ull*   X2u = (ull*)sm;
    float* X2f = sm;
    float* Wd1 = sm + 2 * X2_U;
    float* Wd2 = Wd1 + W1_F;
    float* vec = Wd2 + W2_F;
    float* b1s = vec;        float* g1s = vec + 64;  float* be1s = vec + 128;
    float* b2s = vec + 192;  float* g2s = vec + 256; float* be2s = vec + 320;
    float* W3s = vec + 384;

    const int tid = threadIdx.x;

    // Stage weights with per-row swizzle:
    // element (k, c=cg*8+j) -> k*64 + (j&4 ? 32 : 0) + cg*4 + (j&3)
    for (int i = tid; i < W1_F; i += THREADS) {
        int k = i >> 6, c = i & 63;
        int cg = c >> 3, j = c & 7;
        Wd1[k * 64 + ((j & 4) ? 32 : 0) + cg * 4 + (j & 3)] = W1g[i];
    }
    for (int i = tid; i < W2_F; i += THREADS) {
        int k = i >> 6, c = i & 63;
        int cg = c >> 3, j = c & 7;
        Wd2[k * 64 + ((j & 4) ? 32 : 0) + cg * 4 + (j & 3)] = W2g[i];
    }
    if (tid < 64) {
        b1s[tid] = b1g[tid];  g1s[tid] = g1g[tid];  be1s[tid] = be1g[tid];
        b2s[tid] = b2g[tid];  g2s[tid] = g2g[tid];  be2s[tid] = be2g[tid];
        W3s[tid] = W3g[tid];
    }
    const float b3v = b3g[0];
    const int is32 = g_is32;
    __syncthreads();

    const long long ntiles = (E + TE - 1) / TE;
    const int cg = tid & 7, eg = tid >> 3;
    const int c0 = cg * 8, cg4 = cg * 4, p0 = eg * 4;
    const int lp = tid >> 1, lpar = tid & 1;   // LN / staging mapping

    for (long long tile = blockIdx.x; tile < ntiles; tile += gridDim.x) {
        const long long Eb = tile * (long long)TE;

        // ---- stage X tile: one thread per edge (interleaved pair layout)
        {
            long long e = Eb + tid;
            if (e > E - 1) e = E - 1;
            long long r0, r1;
            if (is32) {
                const int* I = (const int*)eidx;
                r0 = (long long)I[e];  r1 = (long long)I[E + e];
            } else {
                const long long* I = (const long long*)eidx;
                r0 = I[e];  r1 = I[E + e];
            }
            float* xb = X2f + lpar;
            const float4* sp = (const float4*)(nodes + r0 * 64);
            #pragma unroll
            for (int m = 0; m < 16; m++) {
                float4 v = sp[m];
                size_t b = ((size_t)lp * PADK + m * 4) * 2;
                xb[b] = v.x; xb[b + 2] = v.y; xb[b + 4] = v.z; xb[b + 6] = v.w;
            }
            const float4* dp = (const float4*)(nodes + r1 * 64);
            #pragma unroll
            for (int m = 0; m < 16; m++) {
                float4 v = dp[m];
                size_t b = ((size_t)lp * PADK + 64 + m * 4) * 2;
                xb[b] = v.x; xb[b + 2] = v.y; xb[b + 4] = v.z; xb[b + 6] = v.w;
            }
            const float4* ap = (const float4*)(eattr + e * 16);
            #pragma unroll
            for (int m = 0; m < 4; m++) {
                float4 v = ap[m];
                size_t b = ((size_t)lp * PADK + 128 + m * 4) * 2;
                xb[b] = v.x; xb[b + 2] = v.y; xb[b + 4] = v.z; xb[b + 6] = v.w;
            }
        }
        __syncthreads();  // S1: X staged

        // ---- GEMM1: (256 x 144) @ (144 x 64)
        ull acc[4][8];
        #pragma unroll
        for (int i = 0; i < 4; i++)
            #pragma unroll
            for (int j = 0; j < 8; j++) acc[i][j] = 0ULL;
        gemm_tile<KIN>(X2u, Wd1, acc, p0, cg4);
        __syncthreads();  // S2: all X reads done (epi overwrites k-slots 0..63)
        epi_store(acc, X2u, b1s, p0, c0);
        __syncthreads();  // S3: raw H complete

        // ---- LN1 + leaky, in place (one thread per edge)
        // float4 m covers k-slots 2m, 2m+1 (both parities); own parity only.
        {
            const float4* rp = (const float4*)(X2f + (size_t)lp * PADK * 2);
            float s = 0.f, ss = 0.f;
            #pragma unroll
            for (int m = 0; m < 32; m++) {
                float4 v = rp[m];
                float a = lpar ? v.y : v.x;     // k = 2m
                float b = lpar ? v.w : v.z;     // k = 2m+1
                s += a + b;  ss += a * a + b * b;
            }
            float mu  = s * 0.015625f;
            float var = ss * 0.015625f - mu * mu;
            float rs  = rsqrtf(var + LNEPS);
            #pragma unroll
            for (int m = 0; m < 32; m++) {
                float4 v = rp[m];
                float a = lpar ? v.y : v.x;
                float b = lpar ? v.w : v.z;
                int k0 = 2 * m;
                float na = (a - mu) * rs * g1s[k0] + be1s[k0];
                float nb = (b - mu) * rs * g1s[k0 + 1] + be1s[k0 + 1];
                na = fmaxf(na, NEG * na);  nb = fmaxf(nb, NEG * nb);
                size_t bidx = ((size_t)lp * PADK + k0) * 2 + lpar;
                X2f[bidx]     = na;
                X2f[bidx + 2] = nb;
            }
        }
        __syncthreads();  // S4: H normalized, ready for GEMM2

        // ---- GEMM2: (256 x 64) @ (64 x 64)
        #pragma unroll
        for (int i = 0; i < 4; i++)
            #pragma unroll
            for (int j = 0; j < 8; j++) acc[i][j] = 0ULL;
        gemm_tile<HID>(X2u, Wd2, acc, p0, cg4);
        __syncthreads();  // S5: all H reads done
        epi_store(acc, X2u, b2s, p0, c0);
        __syncthreads();  // S6: raw H2 complete

        // ---- LN2 + leaky + dot(W3) + b3 -> global out
        {
            const float4* rp = (const float4*)(X2f + (size_t)lp * PADK * 2);
            float s = 0.f, ss = 0.f;
            #pragma unroll
            for (int m = 0; m < 32; m++) {
                float4 v = rp[m];
                float a = lpar ? v.y : v.x;
                float b = lpar ? v.w : v.z;
                s += a + b;  ss += a * a + b * b;
            }
            float mu  = s * 0.015625f;
            float var = ss * 0.015625f - mu * mu;
            float rs  = rsqrtf(var + LNEPS);
            float accO = 0.f;
            #pragma unroll
            for (int m = 0; m < 32; m++) {
                float4 v = rp[m];
                float a = lpar ? v.y : v.x;
                float b = lpar ? v.w : v.z;
                int k0 = 2 * m;
                float na = (a - mu) * rs * g2s[k0] + be2s[k0];
                float nb = (b - mu) * rs * g2s[k0 + 1] + be2s[k0 + 1];
                na = fmaxf(na, NEG * na);  nb = fmaxf(nb, NEG * nb);
                accO += na * W3s[k0] + nb * W3s[k0 + 1];
            }
            long long e = Eb + tid;
            if (e < E) out[e] = accO + b3v;
        }
        __syncthreads();  // S7: LN2 reads done before next tile's staging
    }
}

// ---------------------------------------------------------------------------
extern "C" void kernel_launch(void* const* d_in, const int* in_sizes, int n_in,
                              void* d_out, int out_size) {
    const float* nodes = (const float*)d_in[0];
    const void*  eidx  = d_in[1];
    const float* eattr = (const float*)d_in[2];
    const float* W1 = (const float*)d_in[3];
    const float* b1 = (const float*)d_in[4];
    const float* g1 = (const float*)d_in[5];
    const float* be1 = (const float*)d_in[6];
    const float* W2 = (const float*)d_in[7];
    const float* b2 = (const float*)d_in[8];
    const float* g2 = (const float*)d_in[9];
    const float* be2 = (const float*)d_in[10];
    const float* W3 = (const float*)d_in[11];
    const float* b3 = (const float*)d_in[12];
    float* out = (float*)d_out;

    const long long E = (long long)in_sizes[2] / 16;
    const unsigned long long n_nodes = (unsigned long long)in_sizes[0] / 64;
    if (E <= 0) return;

    cudaFuncSetAttribute(edge_mlp_kernel,
                         cudaFuncAttributeMaxDynamicSharedMemorySize, SMEM_BYTES);

    int nsm = 148;
    cudaDeviceGetAttribute(&nsm, cudaDevAttrMultiProcessorCount, 0);
    if (nsm <= 0) nsm = 148;

    long long ncheck = E < 2048 ? E : 2048;
    check_idx_kernel<<<1, 256>>>((const long long*)eidx, ncheck, n_nodes);

    long long ntiles = (E + TE - 1) / TE;
    int grid = (ntiles < (long long)nsm) ? (int)ntiles : nsm;
    edge_mlp_kernel<<<grid, THREADS, SMEM_BYTES>>>(
        nodes, eidx, eattr, W1, b1, g1, be1, W2, b2, g2, be2, W3, b3, out, E);
}

// round 17
// speedup vs baseline: 1.1658x; 1.0434x over previous
#include <cuda_runtime.h>
#include <cstdint>

#define THREADS 256
#define TE      256       // edges per tile
#define NPAIR   128       // edge pairs per tile
#define PADK    146       // per-pair k-stride in ull units (even -> 16B alignment)
#define KIN     144
#define HID     64
#define NEG     0.1f
#define LNEPS   1e-5f

typedef unsigned long long ull;

// smem layout (floats)
#define X2_U   (NPAIR * PADK)            // 18688 ull = 37376 floats
#define W1_F   (KIN * HID)               // 9216
#define W2_F   (HID * HID)               // 4096
#define VEC_F  512
#define SMEM_F (2 * X2_U + W1_F + W2_F + VEC_F)   // 51200 floats
#define SMEM_BYTES (SMEM_F * 4)                   // 204800 B

__device__ int g_is32;

// ---------------------------------------------------------------------------
// Detect whether edge_index is really int64 or silently-demoted int32.
__global__ void check_idx_kernel(const long long* __restrict__ idx, long long n,
                                 unsigned long long n_nodes) {
    __shared__ int bad;
    if (threadIdx.x == 0) bad = 0;
    __syncthreads();
    int local = 0;
    for (long long i = threadIdx.x; i < n; i += blockDim.x) {
        if ((unsigned long long)idx[i] >= n_nodes) local = 1;
    }
    if (local) bad = 1;
    __syncthreads();
    if (threadIdx.x == 0) g_is32 = bad;
}

// ---------------------------------------------------------------------------
__device__ __forceinline__ void fma2(ull& d, ull a, ull b) {
    asm("fma.rn.f32x2 %0, %1, %2, %0;" : "+l"(d) : "l"(a), "l"(b));
}
__device__ __forceinline__ ull add2r(ull a, ull b) {
    ull d; asm("add.rn.f32x2 %0, %1, %2;" : "=l"(d) : "l"(a), "l"(b)); return d;
}
__device__ __forceinline__ ull mul2r(ull a, ull b) {
    ull d; asm("mul.rn.f32x2 %0, %1, %2;" : "=l"(d) : "l"(a), "l"(b)); return d;
}
__device__ __forceinline__ ull fma2r(ull a, ull b, ull c) {
    ull d; asm("fma.rn.f32x2 %0, %1, %2, %3;" : "=l"(d) : "l"(a), "l"(b), "l"(c)); return d;
}
__device__ __forceinline__ ull dup2(float v) {
    ull r; asm("mov.b64 %0, {%1, %1};" : "=l"(r) : "f"(v)); return r;
}
__device__ __forceinline__ float2 u2f(ull v) {
    float2 f; asm("mov.b64 {%0, %1}, %2;" : "=f"(f.x), "=f"(f.y) : "l"(v)); return f;
}
__device__ __forceinline__ ull f2u(float x, float y) {
    ull r; asm("mov.b64 %0, {%1, %2};" : "=l"(r) : "f"(x), "f"(y)); return r;
}

// ---------------------------------------------------------------------------
// Software-pipelined GEMM micro-tile: 4 edge-pairs (8 edges) x 8 cols per
// thread, 256 threads. Double-buffered register prefetch with distance 2 k.
// Weights laid out per k-row as [j0..3 of cg0..7][j4..7 of cg0..7] so a
// quarter-warp's LDS.128 covers a contiguous, conflict-free 128B.

struct KBuf {
    ulonglong2 xa, xb, xc, xd;    // 4 pair-rows, 2 k each
    float4 wa0, wb0, wa1, wb1;    // 2 weight rows (k, k+1), this thread's 8 cols
};

__device__ __forceinline__ void load_buf(KBuf& b, const ull* __restrict__ xr,
                                         const float* __restrict__ Wd,
                                         int k, int cg4) {
    b.xa = *(const ulonglong2*)(xr + k);
    b.xb = *(const ulonglong2*)(xr + PADK + k);
    b.xc = *(const ulonglong2*)(xr + 2 * PADK + k);
    b.xd = *(const ulonglong2*)(xr + 3 * PADK + k);
    const float* w = Wd + (size_t)k * 64 + cg4;
    b.wa0 = *(const float4*)(w);
    b.wb0 = *(const float4*)(w + 32);
    b.wa1 = *(const float4*)(w + 64);
    b.wb1 = *(const float4*)(w + 96);
}

__device__ __forceinline__ void compute_buf(const KBuf& b, ull acc[4][8]) {
    {
        ull w0 = dup2(b.wa0.x), w1 = dup2(b.wa0.y), w2 = dup2(b.wa0.z), w3 = dup2(b.wa0.w);
        ull w4 = dup2(b.wb0.x), w5 = dup2(b.wb0.y), w6 = dup2(b.wb0.z), w7 = dup2(b.wb0.w);
        fma2(acc[0][0], b.xa.x, w0); fma2(acc[1][0], b.xb.x, w0);
        fma2(acc[2][0], b.xc.x, w0); fma2(acc[3][0], b.xd.x, w0);
        fma2(acc[0][1], b.xa.x, w1); fma2(acc[1][1], b.xb.x, w1);
        fma2(acc[2][1], b.xc.x, w1); fma2(acc[3][1], b.xd.x, w1);
        fma2(acc[0][2], b.xa.x, w2); fma2(acc[1][2], b.xb.x, w2);
        fma2(acc[2][2], b.xc.x, w2); fma2(acc[3][2], b.xd.x, w2);
        fma2(acc[0][3], b.xa.x, w3); fma2(acc[1][3], b.xb.x, w3);
        fma2(acc[2][3], b.xc.x, w3); fma2(acc[3][3], b.xd.x, w3);
        fma2(acc[0][4], b.xa.x, w4); fma2(acc[1][4], b.xb.x, w4);
        fma2(acc[2][4], b.xc.x, w4); fma2(acc[3][4], b.xd.x, w4);
        fma2(acc[0][5], b.xa.x, w5); fma2(acc[1][5], b.xb.x, w5);
        fma2(acc[2][5], b.xc.x, w5); fma2(acc[3][5], b.xd.x, w5);
        fma2(acc[0][6], b.xa.x, w6); fma2(acc[1][6], b.xb.x, w6);
        fma2(acc[2][6], b.xc.x, w6); fma2(acc[3][6], b.xd.x, w6);
        fma2(acc[0][7], b.xa.x, w7); fma2(acc[1][7], b.xb.x, w7);
        fma2(acc[2][7], b.xc.x, w7); fma2(acc[3][7], b.xd.x, w7);
    }
    {
        ull w0 = dup2(b.wa1.x), w1 = dup2(b.wa1.y), w2 = dup2(b.wa1.z), w3 = dup2(b.wa1.w);
        ull w4 = dup2(b.wb1.x), w5 = dup2(b.wb1.y), w6 = dup2(b.wb1.z), w7 = dup2(b.wb1.w);
        fma2(acc[0][0], b.xa.y, w0); fma2(acc[1][0], b.xb.y, w0);
        fma2(acc[2][0], b.xc.y, w0); fma2(acc[3][0], b.xd.y, w0);
        fma2(acc[0][1], b.xa.y, w1); fma2(acc[1][1], b.xb.y, w1);
        fma2(acc[2][1], b.xc.y, w1); fma2(acc[3][1], b.xd.y, w1);
        fma2(acc[0][2], b.xa.y, w2); fma2(acc[1][2], b.xb.y, w2);
        fma2(acc[2][2], b.xc.y, w2); fma2(acc[3][2], b.xd.y, w2);
        fma2(acc[0][3], b.xa.y, w3); fma2(acc[1][3], b.xb.y, w3);
        fma2(acc[2][3], b.xc.y, w3); fma2(acc[3][3], b.xd.y, w3);
        fma2(acc[0][4], b.xa.y, w4); fma2(acc[1][4], b.xb.y, w4);
        fma2(acc[2][4], b.xc.y, w4); fma2(acc[3][4], b.xd.y, w4);
        fma2(acc[0][5], b.xa.y, w5); fma2(acc[1][5], b.xb.y, w5);
        fma2(acc[2][5], b.xc.y, w5); fma2(acc[3][5], b.xd.y, w5);
        fma2(acc[0][6], b.xa.y, w6); fma2(acc[1][6], b.xb.y, w6);
        fma2(acc[2][6], b.xc.y, w6); fma2(acc[3][6], b.xd.y, w6);
        fma2(acc[0][7], b.xa.y, w7); fma2(acc[1][7], b.xb.y, w7);
        fma2(acc[2][7], b.xc.y, w7); fma2(acc[3][7], b.xd.y, w7);
    }
}

// K must be a multiple of 4 (144, 64 both are).
template<int K>
__device__ __forceinline__ void gemm_tile(const ull* __restrict__ X2u,
                                          const float* __restrict__ Wd,
                                          ull acc[4][8], int p0, int cg4) {
    const ull* xr = X2u + (size_t)p0 * PADK;
    KBuf b0, b1;
    load_buf(b0, xr, Wd, 0, cg4);
    load_buf(b1, xr, Wd, 2, cg4);
    #pragma unroll 1
    for (int k = 0; k < K - 4; k += 4) {
        compute_buf(b0, acc);
        load_buf(b0, xr, Wd, k + 4, cg4);
        compute_buf(b1, acc);
        load_buf(b1, xr, Wd, k + 6, cg4);
    }
    compute_buf(b0, acc);
    compute_buf(b1, acc);
}

// ---------------------------------------------------------------------------
// Fused epilogue: bias + LayerNorm + leaky, entirely in registers.
// The 8 threads (cg=0..7) holding one block of 4 pair-rows are adjacent lanes
// of one warp, so column reductions are shfl_xor butterflies over masks 1,2,4.
// Packs are (even-edge, odd-edge); reductions act on both lanes independently.

// Epilogue 1: normalize and store packed H into X2 k-slots (GEMM2 input).
__device__ __forceinline__ void epi_ln_store(ull acc[4][8], ull* __restrict__ X2u,
                                             const float* __restrict__ bs,
                                             const float* __restrict__ gs,
                                             const float* __restrict__ bes,
                                             int p0, int c0) {
    ull bd[8], gd[8], bed[8];
    #pragma unroll
    for (int j = 0; j < 8; j++) {
        bd[j]  = dup2(bs[c0 + j]);
        gd[j]  = dup2(gs[c0 + j]);
        bed[j] = dup2(bes[c0 + j]);
    }
    const ull inv = dup2(0.015625f);
    #pragma unroll
    for (int i = 0; i < 4; i++) {
        #pragma unroll
        for (int j = 0; j < 8; j++) acc[i][j] = add2r(acc[i][j], bd[j]);
        ull s = acc[i][0], ss = mul2r(acc[i][0], acc[i][0]);
        #pragma unroll
        for (int j = 1; j < 8; j++) {
            s  = add2r(s, acc[i][j]);
            ss = fma2r(acc[i][j], acc[i][j], ss);
        }
        #pragma unroll
        for (int m = 1; m < 8; m <<= 1) {
            s  = add2r(s,  __shfl_xor_sync(0xffffffffu, s,  m));
            ss = add2r(ss, __shfl_xor_sync(0xffffffffu, ss, m));
        }
        float2 mu = u2f(mul2r(s, inv));
        float2 ms = u2f(mul2r(ss, inv));
        float rse = rsqrtf(ms.x - mu.x * mu.x + LNEPS);
        float rso = rsqrtf(ms.y - mu.y * mu.y + LNEPS);
        ull rs2  = f2u(rse, rso);
        ull nmu2 = f2u(-mu.x, -mu.y);
        #pragma unroll
        for (int j = 0; j < 8; j++) {
            ull t = mul2r(add2r(acc[i][j], nmu2), rs2);
            ull n = fma2r(t, gd[j], bed[j]);
            float2 nf = u2f(n);
            nf.x = fmaxf(nf.x, NEG * nf.x);
            nf.y = fmaxf(nf.y, NEG * nf.y);
            X2u[(size_t)(p0 + i) * PADK + (c0 + j)] = f2u(nf.x, nf.y);
        }
    }
}

// Epilogue 2: normalize, leaky, dot with W3, add b3, store to gmem.
__device__ __forceinline__ void epi_ln_out(ull acc[4][8],
                                           const float* __restrict__ bs,
                                           const float* __restrict__ gs,
                                           const float* __restrict__ bes,
                                           const float* __restrict__ w3s,
                                           float b3v, float* __restrict__ out,
                                           long long Eb, long long E,
                                           int p0, int c0, int cg) {
    ull bd[8], gd[8], bed[8], wd[8];
    #pragma unroll
    for (int j = 0; j < 8; j++) {
        bd[j]  = dup2(bs[c0 + j]);
        gd[j]  = dup2(gs[c0 + j]);
        bed[j] = dup2(bes[c0 + j]);
        wd[j]  = dup2(w3s[c0 + j]);
    }
    const ull inv = dup2(0.015625f);
    #pragma unroll
    for (int i = 0; i < 4; i++) {
        #pragma unroll
        for (int j = 0; j < 8; j++) acc[i][j] = add2r(acc[i][j], bd[j]);
        ull s = acc[i][0], ss = mul2r(acc[i][0], acc[i][0]);
        #pragma unroll
        for (int j = 1; j < 8; j++) {
            s  = add2r(s, acc[i][j]);
            ss = fma2r(acc[i][j], acc[i][j], ss);
        }
        #pragma unroll
        for (int m = 1; m < 8; m <<= 1) {
            s  = add2r(s,  __shfl_xor_sync(0xffffffffu, s,  m));
            ss = add2r(ss, __shfl_xor_sync(0xffffffffu, ss, m));
        }
        float2 mu = u2f(mul2r(s, inv));
        float2 ms = u2f(mul2r(ss, inv));
        float rse = rsqrtf(ms.x - mu.x * mu.x + LNEPS);
        float rso = rsqrtf(ms.y - mu.y * mu.y + LNEPS);
        ull rs2  = f2u(rse, rso);
        ull nmu2 = f2u(-mu.x, -mu.y);
        ull dot2 = 0ULL;
        #pragma unroll
        for (int j = 0; j < 8; j++) {
            ull t = mul2r(add2r(acc[i][j], nmu2), rs2);
            ull n = fma2r(t, gd[j], bed[j]);
            float2 nf = u2f(n);
            nf.x = fmaxf(nf.x, NEG * nf.x);
            nf.y = fmaxf(nf.y, NEG * nf.y);
            dot2 = fma2r(f2u(nf.x, nf.y), wd[j], dot2);
        }
        #pragma unroll
        for (int m = 1; m < 8; m <<= 1)
            dot2 = add2r(dot2, __shfl_xor_sync(0xffffffffu, dot2, m));
        if (cg == 0) {
            float2 r = u2f(dot2);
            long long e0 = Eb + 2LL * (p0 + i);
            if (e0 + 1 < E) {
                *(float2*)(out + e0) = make_float2(r.x + b3v, r.y + b3v);
            } else if (e0 < E) {
                out[e0] = r.x + b3v;
            }
        }
    }
}

// ---------------------------------------------------------------------------
extern "C" __global__ void __launch_bounds__(THREADS, 1)
edge_mlp_kernel(const float* __restrict__ nodes,
                const void*  __restrict__ eidx,
                const float* __restrict__ eattr,
                const float* __restrict__ W1g, const float* __restrict__ b1g,
                const float* __restrict__ g1g, const float* __restrict__ be1g,
                const float* __restrict__ W2g, const float* __restrict__ b2g,
                const float* __restrict__ g2g, const float* __restrict__ be2g,
                const float* __restrict__ W3g, const float* __restrict__ b3g,
                float* __restrict__ out, long long E)
{
    extern __shared__ float sm[];
    ull*   X2u = (ull*)sm;
    float* X2f = sm;
    float* Wd1 = sm + 2 * X2_U;
    float* Wd2 = Wd1 + W1_F;
    float* vec = Wd2 + W2_F;
    float* b1s = vec;        float* g1s = vec + 64;  float* be1s = vec + 128;
    float* b2s = vec + 192;  float* g2s = vec + 256; float* be2s = vec + 320;
    float* W3s = vec + 384;

    const int tid = threadIdx.x;

    // Stage weights with per-row swizzle:
    // element (k, c=cg*8+j) -> k*64 + (j&4 ? 32 : 0) + cg*4 + (j&3)
    for (int i = tid; i < W1_F; i += THREADS) {
        int k = i >> 6, c = i & 63;
        int cg = c >> 3, j = c & 7;
        Wd1[k * 64 + ((j & 4) ? 32 : 0) + cg * 4 + (j & 3)] = W1g[i];
    }
    for (int i = tid; i < W2_F; i += THREADS) {
        int k = i >> 6, c = i & 63;
        int cg = c >> 3, j = c & 7;
        Wd2[k * 64 + ((j & 4) ? 32 : 0) + cg * 4 + (j & 3)] = W2g[i];
    }
    if (tid < 64) {
        b1s[tid] = b1g[tid];  g1s[tid] = g1g[tid];  be1s[tid] = be1g[tid];
        b2s[tid] = b2g[tid];  g2s[tid] = g2g[tid];  be2s[tid] = be2g[tid];
        W3s[tid] = W3g[tid];
    }
    const float b3v = b3g[0];
    const int is32 = g_is32;
    __syncthreads();

    const long long ntiles = (E + TE - 1) / TE;
    const int cg = tid & 7, eg = tid >> 3;
    const int c0 = cg * 8, cg4 = cg * 4, p0 = eg * 4;
    const int lp = tid >> 1, lpar = tid & 1;   // staging mapping

    for (long long tile = blockIdx.x; tile < ntiles; tile += gridDim.x) {
        const long long Eb = tile * (long long)TE;

        // ---- stage X tile: one thread per edge (interleaved pair layout)
        {
            long long e = Eb + tid;
            if (e > E - 1) e = E - 1;
            long long r0, r1;
            if (is32) {
                const int* I = (const int*)eidx;
                r0 = (long long)I[e];  r1 = (long long)I[E + e];
            } else {
                const long long* I = (const long long*)eidx;
                r0 = I[e];  r1 = I[E + e];
            }
            float* xb = X2f + lpar;
            const float4* sp = (const float4*)(nodes + r0 * 64);
            #pragma unroll
            for (int m = 0; m < 16; m++) {
                float4 v = sp[m];
                size_t b = ((size_t)lp * PADK + m * 4) * 2;
                xb[b] = v.x; xb[b + 2] = v.y; xb[b + 4] = v.z; xb[b + 6] = v.w;
            }
            const float4* dp = (const float4*)(nodes + r1 * 64);
            #pragma unroll
            for (int m = 0; m < 16; m++) {
                float4 v = dp[m];
                size_t b = ((size_t)lp * PADK + 64 + m * 4) * 2;
                xb[b] = v.x; xb[b + 2] = v.y; xb[b + 4] = v.z; xb[b + 6] = v.w;
            }
            const float4* ap = (const float4*)(eattr + e * 16);
            #pragma unroll
            for (int m = 0; m < 4; m++) {
                float4 v = ap[m];
                size_t b = ((size_t)lp * PADK + 128 + m * 4) * 2;
                xb[b] = v.x; xb[b + 2] = v.y; xb[b + 4] = v.z; xb[b + 6] = v.w;
            }
        }
        __syncthreads();  // S1: X staged

        // ---- GEMM1: (256 x 144) @ (144 x 64)
        ull acc[4][8];
        #pragma unroll
        for (int i = 0; i < 4; i++)
            #pragma unroll
            for (int j = 0; j < 8; j++) acc[i][j] = 0ULL;
        gemm_tile<KIN>(X2u, Wd1, acc, p0, cg4);
        __syncthreads();  // S2: all X reads done (epi overwrites k-slots 0..63)

        // ---- fused bias + LN1 + leaky -> normalized H into X2 (registers only)
        epi_ln_store(acc, X2u, b1s, g1s, be1s, p0, c0);
        __syncthreads();  // S3: H ready for GEMM2

        // ---- GEMM2: (256 x 64) @ (64 x 64)
        #pragma unroll
        for (int i = 0; i < 4; i++)
            #pragma unroll
            for (int j = 0; j < 8; j++) acc[i][j] = 0ULL;
        gemm_tile<HID>(X2u, Wd2, acc, p0, cg4);

        // ---- fused bias + LN2 + leaky + dot(W3) + b3 -> gmem (no smem writes)
        epi_ln_out(acc, b2s, g2s, be2s, W3s, b3v, out, Eb, E, p0, c0, cg);
        __syncthreads();  // S4: GEMM2 reads done before next tile's staging
    }
}

// ---------------------------------------------------------------------------
extern "C" void kernel_launch(void* const* d_in, const int* in_sizes, int n_in,
                              void* d_out, int out_size) {
    const float* nodes = (const float*)d_in[0];
    const void*  eidx  = d_in[1];
    const float* eattr = (const float*)d_in[2];
    const float* W1 = (const float*)d_in[3];
    const float* b1 = (const float*)d_in[4];
    const float* g1 = (const float*)d_in[5];
    const float* be1 = (const float*)d_in[6];
    const float* W2 = (const float*)d_in[7];
    const float* b2 = (const float*)d_in[8];
    const float* g2 = (const float*)d_in[9];
    const float* be2 = (const float*)d_in[10];
    const float* W3 = (const float*)d_in[11];
    const float* b3 = (const float*)d_in[12];
    float* out = (float*)d_out;

    const long long E = (long long)in_sizes[2] / 16;
    const unsigned long long n_nodes = (unsigned long long)in_sizes[0] / 64;
    if (E <= 0) return;

    cudaFuncSetAttribute(edge_mlp_kernel,
                         cudaFuncAttributeMaxDynamicSharedMemorySize, SMEM_BYTES);

    int nsm = 148;
    cudaDeviceGetAttribute(&nsm, cudaDevAttrMultiProcessorCount, 0);
    if (nsm <= 0) nsm = 148;

    long long ncheck = E < 2048 ? E : 2048;
    check_idx_kernel<<<1, 256>>>((const long long*)eidx, ncheck, n_nodes);

    long long ntiles = (E + TE - 1) / TE;
    int grid = (ntiles < (long long)nsm) ? (int)ntiles : nsm;
    edge_mlp_kernel<<<grid, THREADS, SMEM_BYTES>>>(
        nodes, eidx, eattr, W1, b1, g1, be1, W2, b2, g2, be2, W3, b3, out, E);
}